// round 16
// baseline (speedup 1.0000x reference)
#include <cuda_runtime.h>
#include <cstdint>

// Two-pass RNN.  h_t = tanh( xproj[t] + h_{t-1} @ W_hh^T ),  out = h_{T-1}
// B=4096, T=512, IN=15, HID=20.
//
// R15 showed the binder is SHFL/MIO wavefront throughput (~0.57 wf/cyc at
// 9.2 warps/SM). This version minimizes per-step MIO in the recurrence and
// raises warps/SM in both passes:
//  Pass-1: xproj to GMEM scratch [b][t][pair]; T split across 2 warps/CTA
//          (18.5 warps/SM) to saturate the MIO pipe on the same traffic.
//  Pass-2: BPW=2 (2048 warps, 13.8/SM) — warp instr cost is density-
//          independent, so lower density = more chain-hiding warps free.
//          Per step: 1 private LDG.64 (xproj FIFO, static 4-slot) +
//          5 LDS.128 h-gather (1 wf each after broadcast dedup) + STS.64.

#define T_STEPS 512
#define BATCH   4096
#define N_IN    15
#define N_HID   20
#define FULL    0xffffffffu

typedef unsigned long long ull;

// scratch: [b][t][pair]  = 4096*512*10*8B = 167,772,160 B
__device__ ull g_xproj[BATCH][T_STEPS][10];

__device__ __forceinline__ ull pack2(float lo, float hi) {
    ull r; asm("mov.b64 %0, {%1, %2};" : "=l"(r) : "f"(lo), "f"(hi)); return r;
}
__device__ __forceinline__ ull fma2(ull a, ull b, ull c) {
    ull d; asm("fma.rn.f32x2 %0, %1, %2, %3;" : "=l"(d) : "l"(a), "l"(b), "l"(c)); return d;
}
__device__ __forceinline__ ull add2(ull a, ull b) {
    ull d; asm("add.rn.f32x2 %0, %1, %2;" : "=l"(d) : "l"(a), "l"(b)); return d;
}
__device__ __forceinline__ float hsum2(ull a) {
    float lo, hi; asm("mov.b64 {%0, %1}, %2;" : "=f"(lo), "=f"(hi) : "l"(a));
    return lo + hi;
}
__device__ __forceinline__ void unpack2(ull a, float& lo, float& hi) {
    asm("mov.b64 {%0, %1}, %2;" : "=f"(lo), "=f"(hi) : "l"(a));
}
__device__ __forceinline__ float tanh_mufu(float z) {
    float r; asm("tanh.approx.f32 %0, %1;" : "=f"(r) : "f"(z)); return r;
}

// -------- Pass 1: xproj[b][t][tl] = x_t·Wih[2tl,2tl+1] + bias ---------------
// Block = 64 thr = 2 warps over the SAME 3 batches; warp w handles
// t in [w*256, w*256+256). Within a warp: 3 groups x 10 lanes (R15 layout),
// loader lanes tl<8 hold a static 4-slot x-pair FIFO, consumers shfl64.
#define P1_BPW    3
#define P1_SEG    (T_STEPS / 2)            // 256
#define P1_CTAS   ((BATCH + P1_BPW - 1) / P1_BPW)   // 1366

__global__ __launch_bounds__(64, 9)
void rnn_xproj_kernel(const float* __restrict__ feature,
                      const float* __restrict__ W_ih,
                      const float* __restrict__ b_ih,
                      const float* __restrict__ b_hh)
{
    const int wid  = threadIdx.x >> 5;           // t-segment selector
    const int lane = threadIdx.x & 31;
    const int g    = lane / 10;
    const int tl   = lane % 10;
    const bool active = (g < P1_BPW);
    const int  gc  = active ? g : 0;
    const int  base = gc * 10;
    const int  b   = blockIdx.x * P1_BPW + gc;
    const bool valid = active && (b < BATCH);
    const int j0 = 2 * tl, j1 = 2 * tl + 1;
    const int t0 = wid * P1_SEG;

    const bool xl  = valid && (tl < 8);          // loader of pair (x2tl, x2tl+1)
    const bool xhi = (tl < 7);                   // pair 7 = (x14, 0)

    ull wx0[8], wx1[8];
#pragma unroll
    for (int p = 0; p < 7; p++) {
        wx0[p] = pack2(W_ih[j0 * N_IN + 2 * p], W_ih[j0 * N_IN + 2 * p + 1]);
        wx1[p] = pack2(W_ih[j1 * N_IN + 2 * p], W_ih[j1 * N_IN + 2 * p + 1]);
    }
    wx0[7] = pack2(W_ih[j0 * N_IN + 14], 0.0f);
    wx1[7] = pack2(W_ih[j1 * N_IN + 14], 0.0f);
    const ull bias2_0 = pack2(b_ih[j0] + b_hh[j0], 0.0f);
    const ull bias2_1 = pack2(b_ih[j1] + b_hh[j1], 0.0f);

    const float* xrow = feature + (size_t)(valid ? b : 0) * T_STEPS * N_IN;

    // static 4-slot FIFO: slot q holds x_t pair with (t-t0)&3==q
    ull fx[4];
#pragma unroll
    for (int q = 0; q < 4; q++)
        fx[q] = xl ? pack2(xrow[(t0 + q) * N_IN + 2 * tl],
                           xhi ? xrow[(t0 + q) * N_IN + 2 * tl + 1] : 0.0f) : 0ull;

#pragma unroll 4
    for (int tt = 0; tt < P1_SEG; tt++) {
        const int t = t0 + tt;
        const int q = tt & 3;

        ull xp[8];
#pragma unroll
        for (int p = 0; p < 8; p++)
            xp[p] = __shfl_sync(FULL, fx[q], base + p);

        // refill slot q for t+4 (scalar LDG.32 — offset parity varies)
        if (xl && (tt + 4) < P1_SEG) {
            const float* r4 = xrow + (t + 4) * N_IN + 2 * tl;
            fx[q] = pack2(r4[0], xhi ? r4[1] : 0.0f);
        }

        ull a0 = bias2_0, c0 = 0ull, a1 = bias2_1, c1 = 0ull;
#pragma unroll
        for (int k = 0; k < 8; k++) {
            if (k & 1) { c0 = fma2(xp[k], wx0[k], c0); c1 = fma2(xp[k], wx1[k], c1); }
            else       { a0 = fma2(xp[k], wx0[k], a0); a1 = fma2(xp[k], wx1[k], a1); }
        }
        const float z0 = hsum2(add2(a0, c0));
        const float z1 = hsum2(add2(a1, c1));

        if (valid) g_xproj[b][t][tl] = pack2(z0, z1);
    }
}

// -------- Pass 2: the recurrence (BPW=2 for chain hiding) -------------------
#define P2_BPW   2
#define P2_CTAS  (BATCH / P2_BPW)          // 2048

__global__ __launch_bounds__(32, 14)
void rnn_recur_kernel(const float* __restrict__ W_hh,
                      float* __restrict__ out)
{
    // h pairs, double buffered; rows are 80B (16B multiple) apart
    __shared__ __align__(16) ull hsm[2][P2_BPW][10];

    const int lane = threadIdx.x & 31;
    const int slot = lane / 10;                  // 0,1 batch slots; >=2 idle
    const int tl   = lane % 10;
    const bool active = (slot < P2_BPW);
    const int  sc  = active ? slot : 0;
    const int  b   = blockIdx.x * P2_BPW + sc;   // < 4096 exactly
    const int j0 = 2 * tl, j1 = 2 * tl + 1;

    ull wh0[10], wh1[10];
#pragma unroll
    for (int p = 0; p < 10; p++) {
        wh0[p] = pack2(W_hh[j0 * N_HID + 2 * p], W_hh[j0 * N_HID + 2 * p + 1]);
        wh1[p] = pack2(W_hh[j1 * N_HID + 2 * p], W_hh[j1 * N_HID + 2 * p + 1]);
    }

    if (active) hsm[0][sc][tl] = 0ull;           // h_{-1} = 0

    // private xproj stream (sequential 80B/step); static 4-slot FIFO
    const ull* xq = &g_xproj[b][0][tl];
    ull fx[4];
#pragma unroll
    for (int q = 0; q < 4; q++)
        fx[q] = xq[q * 10];

    ull hpk = 0ull;

#pragma unroll 4
    for (int t = 0; t < T_STEPS; t++) {
        const int p = t & 1;
        const int q = t & 3;
        __syncwarp();   // order prev STS(buf p) before LDS(buf p); WAR on p^1

        // h_{t-1} gather: 5x LDS.128, 2 unique addresses/warp -> ~1 wf each
        ull hp[10];
        {
            const ulonglong2* hv = (const ulonglong2*)hsm[p][sc];
            ulonglong2 v0 = hv[0], v1 = hv[1], v2 = hv[2], v3 = hv[3], v4 = hv[4];
            hp[0] = v0.x; hp[1] = v0.y; hp[2] = v1.x; hp[3] = v1.y;
            hp[4] = v2.x; hp[5] = v2.y; hp[6] = v3.x; hp[7] = v3.y;
            hp[8] = v4.x; hp[9] = v4.y;
        }

        // consume slot q (loaded at t-4), refill for t+4 (full DRAM cover)
        float x0, x1; unpack2(fx[q], x0, x1);
        if ((t + 4) < T_STEPS) fx[q] = xq[(t + 4) * 10];

        // 20 fma2 over 4 chains (depth 5)
        ull a0 = pack2(x0, 0.0f), c0 = 0ull;
        ull a1 = pack2(x1, 0.0f), c1 = 0ull;
#pragma unroll
        for (int k = 0; k < 10; k++) {
            if (k & 1) { c0 = fma2(hp[k], wh0[k], c0); c1 = fma2(hp[k], wh1[k], c1); }
            else       { a0 = fma2(hp[k], wh0[k], a0); a1 = fma2(hp[k], wh1[k], a1); }
        }
        const float z0 = hsum2(add2(a0, c0));
        const float z1 = hsum2(add2(a1, c1));

        hpk = pack2(tanh_mufu(z0), tanh_mufu(z1));

        if (active) hsm[p ^ 1][sc][tl] = hpk;    // STS.64
    }

    if (active) {
        float lo, hi; unpack2(hpk, lo, hi);
        *(float2*)&out[b * N_HID + j0] = make_float2(lo, hi);  // STG.64
    }
}

extern "C" void kernel_launch(void* const* d_in, const int* in_sizes, int n_in,
                              void* d_out, int out_size)
{
    const float* feature = (const float*)d_in[0];
    const float* W_ih    = (const float*)d_in[1];
    const float* W_hh    = (const float*)d_in[2];
    const float* b_ih    = (const float*)d_in[3];
    const float* b_hh    = (const float*)d_in[4];
    float* out = (float*)d_out;

    rnn_xproj_kernel<<<P1_CTAS, 64>>>(feature, W_ih, b_ih, b_hh);
    rnn_recur_kernel<<<P2_CTAS, 32>>>(W_hh, out);
}

// round 17
// speedup vs baseline: 1.1673x; 1.1673x over previous
#include <cuda_runtime.h>
#include <cstdint>

// Fused RNN. h_t = tanh(x_t @ W_ih^T + b_ih + b_hh + h_{t-1} @ W_hh^T)
// out = h_{T-1}.  B=4096, T=512, IN=15, HID=20.
//
// MIO model (validated R9/R13/R15/R16): time ~ total comm ops / throughput,
// SHFL.32 ~0.53/cyc/SM, LDS wavefront ~0.9/cyc/SM. LDS moves a ull in 2 wf
// (2.2 cyc) vs shfl64's 2 slots (3.8 cyc) -> ALL exchange goes through
// warp-local smem here. 1366 single-warp CTAs (minimum warps for B=4096 at
// 3 batches/warp) x ~43 wf/step ~= 440 cyc/step ~= 115us predicted.
// Static 4-slot x FIFO (R13-proven, full DRAM cover), MUFU.TANH, f32x2 FMA.

#define T_STEPS 512
#define BATCH   4096
#define N_IN    15
#define N_HID   20
#define BPW     3
#define THREADS 32
#define N_CTAS  ((BATCH + BPW - 1) / BPW)   // 1366

typedef unsigned long long ull;

__device__ __forceinline__ ull pack2(float lo, float hi) {
    ull r; asm("mov.b64 %0, {%1, %2};" : "=l"(r) : "f"(lo), "f"(hi)); return r;
}
__device__ __forceinline__ ull fma2(ull a, ull b, ull c) {
    ull d; asm("fma.rn.f32x2 %0, %1, %2, %3;" : "=l"(d) : "l"(a), "l"(b), "l"(c)); return d;
}
__device__ __forceinline__ ull add2(ull a, ull b) {
    ull d; asm("add.rn.f32x2 %0, %1, %2;" : "=l"(d) : "l"(a), "l"(b)); return d;
}
__device__ __forceinline__ float hsum2(ull a) {
    float lo, hi; asm("mov.b64 {%0, %1}, %2;" : "=f"(lo), "=f"(hi) : "l"(a));
    return lo + hi;
}
__device__ __forceinline__ float tanh_mufu(float z) {
    float r; asm("tanh.approx.f32 %0, %1;" : "=f"(r) : "f"(z)); return r;
}

__global__ __launch_bounds__(THREADS, 10)
void rnn_lds_kernel(const float* __restrict__ feature,
                    const float* __restrict__ W_ih,
                    const float* __restrict__ W_hh,
                    const float* __restrict__ b_ih,
                    const float* __restrict__ b_hh,
                    float* __restrict__ out)
{
    // warp-local staging, double buffered; rows 16B-aligned
    __shared__ __align__(16) float xs[2][BPW][16];  // x_t pairs (8 ull slots)
    __shared__ __align__(16) ull   hs[2][BPW][10];  // h_{t-1} pairs (80B rows)

    const int lane = threadIdx.x & 31;
    const int g    = lane / 10;                  // 0..2 batch slot (3 = riders)
    const int tl   = lane % 10;
    const bool active = (g < BPW);
    const int  gc  = active ? g : 0;
    const int  b   = blockIdx.x * BPW + gc;
    const bool valid = active && (b < BATCH);
    const int j0 = 2 * tl, j1 = 2 * tl + 1;

    // x-loader role: lane tl<8 supplies packed pair (x[2tl], x[2tl+1])
    const bool xl  = valid && (tl < 8);
    const bool xhi = (tl < 7);                   // pair 7 = (x14, 0)

    // ---- loop-invariant packed weights (f32x2 k-pairs) ----
    ull wx0[8], wx1[8], wh0[10], wh1[10];
#pragma unroll
    for (int p = 0; p < 7; p++) {
        wx0[p] = pack2(W_ih[j0 * N_IN + 2 * p], W_ih[j0 * N_IN + 2 * p + 1]);
        wx1[p] = pack2(W_ih[j1 * N_IN + 2 * p], W_ih[j1 * N_IN + 2 * p + 1]);
    }
    wx0[7] = pack2(W_ih[j0 * N_IN + 14], 0.0f);
    wx1[7] = pack2(W_ih[j1 * N_IN + 14], 0.0f);
#pragma unroll
    for (int p = 0; p < 10; p++) {
        wh0[p] = pack2(W_hh[j0 * N_HID + 2 * p], W_hh[j0 * N_HID + 2 * p + 1]);
        wh1[p] = pack2(W_hh[j1 * N_HID + 2 * p], W_hh[j1 * N_HID + 2 * p + 1]);
    }
    const ull bias2_0 = pack2(b_ih[j0] + b_hh[j0], 0.0f);
    const ull bias2_1 = pack2(b_ih[j1] + b_hh[j1], 0.0f);

    // ---- prologue ----
    const float* xrow = feature + (size_t)(valid ? b : 0) * T_STEPS * N_IN;

    // xs[0] <- x_0 pairs (pair 7 carries the zero pad)
    if (xl)
        ((ull*)xs[0][gc])[tl] = pack2(xrow[2 * tl],
                                      xhi ? xrow[2 * tl + 1] : 0.0f);
    if (active) hs[0][gc][tl] = 0ull;            // h_{-1} = 0

    // static FIFO: at step t, slot s=(t+1)&3 is PUBLISHED as x_{t+1}, then
    // refilled with x_{t+5} (republished at t+4 -> 4-step DRAM cover).
    // init: fx[q] = x_q (q=1..3), fx[0] = x_4 (first published at t=3).
    ull fx[4];
    fx[0] = xl ? pack2(xrow[4 * N_IN + 2 * tl],
                       xhi ? xrow[4 * N_IN + 2 * tl + 1] : 0.0f) : 0ull;
#pragma unroll
    for (int q = 1; q < 4; q++)
        fx[q] = xl ? pack2(xrow[q * N_IN + 2 * tl],
                           xhi ? xrow[q * N_IN + 2 * tl + 1] : 0.0f) : 0ull;

    ull hpk = 0ull;   // this lane's packed (h[2tl], h[2tl+1])

#pragma unroll 4
    for (int t = 0; t < T_STEPS; t++) {
        const int p = t & 1;
        const int s = (t + 1) & 3;
        __syncwarp();   // prologue/prev-step stores visible; WAR on p^1 done

        // publish x_{t+1} into buffer p^1 (STS.64), then refill slot s with
        // x_{t+5} via two scalar LDG.32 (offset parity varies; LDG.64 traps)
        if (xl) ((ull*)xs[p ^ 1][gc])[tl] = fx[s];
        if (xl && (t + 5) < T_STEPS) {
            const float* r5 = xrow + (t + 5) * N_IN + 2 * tl;
            fx[s] = pack2(r5[0], xhi ? r5[1] : 0.0f);
        }

        // gather x_t (4x LDS.128) and h_{t-1} (5x LDS.128) from buffer p
        ull xp[8], hp[10];
        {
            const ulonglong2* xv = (const ulonglong2*)xs[p][gc];
            ulonglong2 v0 = xv[0], v1 = xv[1], v2 = xv[2], v3 = xv[3];
            xp[0] = v0.x; xp[1] = v0.y; xp[2] = v1.x; xp[3] = v1.y;
            xp[4] = v2.x; xp[5] = v2.y; xp[6] = v3.x; xp[7] = v3.y;
        }
        {
            const ulonglong2* hv = (const ulonglong2*)hs[p][gc];
            ulonglong2 v0 = hv[0], v1 = hv[1], v2 = hv[2], v3 = hv[3], v4 = hv[4];
            hp[0] = v0.x; hp[1] = v0.y; hp[2] = v1.x; hp[3] = v1.y;
            hp[4] = v2.x; hp[5] = v2.y; hp[6] = v3.x; hp[7] = v3.y;
            hp[8] = v4.x; hp[9] = v4.y;
        }

        // 36 fma2 over 4 independent chains (depth ~9)
        ull a0 = bias2_0, c0 = 0ull, a1 = bias2_1, c1 = 0ull;
#pragma unroll
        for (int k = 0; k < 8; k++) {
            if (k & 1) { c0 = fma2(xp[k], wx0[k], c0); c1 = fma2(xp[k], wx1[k], c1); }
            else       { a0 = fma2(xp[k], wx0[k], a0); a1 = fma2(xp[k], wx1[k], a1); }
        }
#pragma unroll
        for (int k = 0; k < 10; k++) {
            if (k & 1) { c0 = fma2(hp[k], wh0[k], c0); c1 = fma2(hp[k], wh1[k], c1); }
            else       { a0 = fma2(hp[k], wh0[k], a0); a1 = fma2(hp[k], wh1[k], a1); }
        }
        const float z0 = hsum2(add2(a0, c0));
        const float z1 = hsum2(add2(a1, c1));

        hpk = pack2(tanh_mufu(z0), tanh_mufu(z1));

        if (active) hs[p ^ 1][gc][tl] = hpk;     // publish h_t (STS.64)
    }

    if (valid) {
        float lo, hi;
        asm("mov.b64 {%0, %1}, %2;" : "=f"(lo), "=f"(hi) : "l"(hpk));
        *(float2*)&out[b * N_HID + j0] = make_float2(lo, hi);  // STG.64
    }
}

extern "C" void kernel_launch(void* const* d_in, const int* in_sizes, int n_in,
                              void* d_out, int out_size)
{
    const float* feature = (const float*)d_in[0];
    const float* W_ih    = (const float*)d_in[1];
    const float* W_hh    = (const float*)d_in[2];
    const float* b_ih    = (const float*)d_in[3];
    const float* b_hh    = (const float*)d_in[4];
    float* out = (float*)d_out;

    rnn_lds_kernel<<<N_CTAS, THREADS>>>(feature, W_ih, W_hh, b_ih, b_hh, out);
}